// round 16
// baseline (speedup 1.0000x reference)
#include <cuda_runtime.h>
#include <cuda_fp16.h>
#include <math.h>
#include <stdint.h>

#define B_  4
#define T_  2048
#define C_  2048
#define NH  16
#define NKV 4
#define HD  128
#define KVW 1024
#define M_  (B_ * T_)   // 8192

// ---------------- scratch (no allocations allowed) ----------------
__device__ __half g_xh[(size_t)M_ * C_];          // x fp16
__device__ __half g_qh[(size_t)M_ * C_];          // q fp16 (normalized in place)
__device__ __half g_kh[(size_t)M_ * 512];         // k fp16 (normalized in place)
__device__ __half g_vh[(size_t)M_ * 512];         // v fp16
__device__ __half g_yh[(size_t)M_ * C_];          // attn out fp16
__device__ __half g_wqkvt[(size_t)3072 * C_];     // [WqT (2048 rows) | WkvT (1024 rows)] [N][K]
__device__ __half g_wpt[(size_t)C_ * C_];         // WprojT [N][K]

// ================= helpers =================
__device__ __forceinline__ uint32_t smem_to_u32(const void* p) {
    uint32_t a;
    asm("{ .reg .u64 t; cvta.to.shared.u64 t, %1; cvt.u32.u64 %0, t; }"
        : "=r"(a) : "l"(p));
    return a;
}
#define SWZ(off) ((off) ^ (((off) >> 3) & 0x70))

__device__ __forceinline__ void ldm4(uint32_t* r, uint32_t addr) {
    asm volatile("ldmatrix.sync.aligned.m8n8.x4.shared.b16 {%0,%1,%2,%3}, [%4];"
        : "=r"(r[0]), "=r"(r[1]), "=r"(r[2]), "=r"(r[3]) : "r"(addr));
}
__device__ __forceinline__ void ldm2(uint32_t* r, uint32_t addr) {
    asm volatile("ldmatrix.sync.aligned.m8n8.x2.shared.b16 {%0,%1}, [%2];"
        : "=r"(r[0]), "=r"(r[1]) : "r"(addr));
}
__device__ __forceinline__ void ldm4t(uint32_t* r, uint32_t addr) {
    asm volatile("ldmatrix.sync.aligned.m8n8.x4.trans.shared.b16 {%0,%1,%2,%3}, [%4];"
        : "=r"(r[0]), "=r"(r[1]), "=r"(r[2]), "=r"(r[3]) : "r"(addr));
}
__device__ __forceinline__ void mma_f16(float* c, const uint32_t* a, const uint32_t* b) {
    asm volatile("mma.sync.aligned.m16n8k16.row.col.f32.f16.f16.f32 "
        "{%0,%1,%2,%3}, {%4,%5,%6,%7}, {%8,%9}, {%0,%1,%2,%3};"
        : "+f"(c[0]), "+f"(c[1]), "+f"(c[2]), "+f"(c[3])
        : "r"(a[0]), "r"(a[1]), "r"(a[2]), "r"(a[3]), "r"(b[0]), "r"(b[1]));
}
__device__ __forceinline__ void cp16(uint32_t dst, const void* src) {
    asm volatile("cp.async.cg.shared.global [%0], [%1], 16;" :: "r"(dst), "l"(src));
}
#define CP_COMMIT() asm volatile("cp.async.commit_group;" ::: "memory")
#define CP_WAIT0()  asm volatile("cp.async.wait_group 0;" ::: "memory")
#define CP_WAIT1()  asm volatile("cp.async.wait_group 1;" ::: "memory")
#define CP_WAIT2()  asm volatile("cp.async.wait_group 2;" ::: "memory")

__device__ __forceinline__ uint32_t pack_h2(float x, float y) {
    __half2 t = __float22half2_rn(make_float2(x, y));
    return *(uint32_t*)&t;
}

// ================= fused staging: x convert + 3 weight transposes =================
__device__ __forceinline__ void transpose_tile(const float* __restrict__ W,
                                               __half* __restrict__ Tt,
                                               int K, int N, int n0, int k0, int tid)
{
    __shared__ float t[32][33];
    int tx = tid & 31, ty = tid >> 5;
#pragma unroll
    for (int j = 0; j < 4; j++)
        t[ty + 8 * j][tx] = W[(size_t)(k0 + ty + 8 * j) * N + n0 + tx];
    __syncthreads();
#pragma unroll
    for (int j = 0; j < 4; j++)
        Tt[(size_t)(n0 + ty + 8 * j) * K + k0 + tx] = __float2half_rn(t[tx][ty + 8 * j]);
}

__global__ void __launch_bounds__(256) stage_all(const float* __restrict__ x,
                                                 const float* __restrict__ Wq,
                                                 const float* __restrict__ Wkv,
                                                 const float* __restrict__ Wproj)
{
    const int bid = blockIdx.x, tid = threadIdx.x;
    if (bid < 2048) {
        const float4* src = (const float4*)x;
        uint2* dst = (uint2*)g_xh;
        const int n4 = M_ * C_ / 4;
        for (int i = bid * 256 + tid; i < n4; i += 2048 * 256) {
            float4 v = src[i];
            dst[i] = make_uint2(pack_h2(v.x, v.y), pack_h2(v.z, v.w));
        }
    } else if (bid < 6144) {
        int b = bid - 2048;
        transpose_tile(Wq, g_wqkvt, C_, C_, (b & 63) * 32, (b >> 6) * 32, tid);
    } else if (bid < 8192) {
        int b = bid - 6144;
        transpose_tile(Wkv, g_wqkvt + (size_t)2048 * C_, C_, KVW,
                       (b & 31) * 32, (b >> 5) * 32, tid);
    } else {
        int b = bid - 8192;
        transpose_tile(Wproj, g_wpt, C_, C_, (b & 63) * 32, (b >> 6) * 32, tid);
    }
}

// ================= HMMA fp16 GEMM, 2-stage (R12 mainloop) =================
// MODE 0: fp32 out (outp, stride No). MODE 3: fused qkv epilogue select by col0.
__device__ __forceinline__ void cp_panel(uint32_t dstBase, const __half* __restrict__ src,
                                         int ldk, int row0, int k0)
{
    int tid = threadIdx.x;
#pragma unroll
    for (int i = 0; i < 4; i++) {
        int l = tid + 256 * i;
        int r = l >> 3, ch = l & 7;
        cp16(dstBase + SWZ(r * 128 + ch * 16), src + (size_t)(row0 + r) * ldk + k0 + ch * 8);
    }
}

template<int MODE>
__global__ void __launch_bounds__(256) gemm_mma(const __half* __restrict__ A,
                                                const __half* __restrict__ Bt,
                                                void* __restrict__ outp,
                                                int K, int No)
{
    extern __shared__ char sm[];
    uint32_t sb = smem_to_u32(sm);
    const int tid = threadIdx.x, wid = tid >> 5, lane = tid & 31;
    const int row0 = blockIdx.y * 128, col0 = blockIdx.x * 128;
    const int wm = (wid >> 2) * 64;
    const int wn = (wid & 3) * 32;

    float acc[4][4][4];
#pragma unroll
    for (int a = 0; a < 4; a++)
#pragma unroll
        for (int b = 0; b < 4; b++)
#pragma unroll
            for (int c = 0; c < 4; c++) acc[a][b][c] = 0.f;

    const int KIT = K >> 6;
#pragma unroll
    for (int p = 0; p < 2; p++) {
        uint32_t st = sb + p * 32768;
        cp_panel(st,         A,  K, row0, p * 64);
        cp_panel(st + 16384, Bt, K, col0, p * 64);
        CP_COMMIT();
    }

    for (int kc = 0; kc < KIT; kc++) {
        if (kc == KIT - 1) CP_WAIT0(); else CP_WAIT1();
        __syncthreads();

        uint32_t st = sb + (kc & 1) * 32768;
#pragma unroll
        for (int ks = 0; ks < 4; ks++) {
            uint32_t af[4][4], bf[4][2];
            const int arow = wm + (lane & 15);
            const int acol = ks * 32 + ((lane >> 4) & 1) * 16;
#pragma unroll
            for (int mt = 0; mt < 4; mt++)
                ldm4(af[mt], st + SWZ((uint32_t)(arow + mt * 16) * 128 + acol));
            const int brow = wn + (lane & 7);
            const int bcol = ks * 32 + ((lane >> 3) & 1) * 16;
#pragma unroll
            for (int nt = 0; nt < 4; nt++)
                ldm2(bf[nt], st + 16384 + SWZ((uint32_t)(brow + nt * 8) * 128 + bcol));
#pragma unroll
            for (int mt = 0; mt < 4; mt++)
#pragma unroll
                for (int nt = 0; nt < 4; nt++)
                    mma_f16(acc[mt][nt], af[mt], bf[nt]);
        }
        __syncthreads();

        if (kc + 2 < KIT) {
            uint32_t st2 = sb + (kc & 1) * 32768;
            int k0 = (kc + 2) * 64;
            cp_panel(st2,         A,  K, row0, k0);
            cp_panel(st2 + 16384, Bt, K, col0, k0);
            CP_COMMIT();
        }
    }

    const int r0 = row0 + wm + (lane >> 2);
    if (MODE == 0) {
        float* o = (float*)outp;
        const int c0 = col0 + wn + (lane & 3) * 2;
#pragma unroll
        for (int mt = 0; mt < 4; mt++)
#pragma unroll
            for (int nt = 0; nt < 4; nt++) {
                *(float2*)(o + (size_t)(r0 + mt * 16) * No + c0 + nt * 8) =
                    make_float2(acc[mt][nt][0], acc[mt][nt][1]);
                *(float2*)(o + (size_t)(r0 + mt * 16 + 8) * No + c0 + nt * 8) =
                    make_float2(acc[mt][nt][2], acc[mt][nt][3]);
            }
    } else {
        __half* o;
        int stride, cbase;
        if (col0 < 2048)      { o = g_qh; stride = C_;  cbase = col0; }
        else if (col0 < 2560) { o = g_kh; stride = 512; cbase = col0 - 2048; }
        else                  { o = g_vh; stride = 512; cbase = col0 - 2560; }
        const int c0 = cbase + wn + (lane & 3) * 2;
#pragma unroll
        for (int mt = 0; mt < 4; mt++)
#pragma unroll
            for (int nt = 0; nt < 4; nt++) {
                *(uint32_t*)(o + (size_t)(r0 + mt * 16) * stride + c0 + nt * 8) =
                    pack_h2(acc[mt][nt][0], acc[mt][nt][1]);
                *(uint32_t*)(o + (size_t)(r0 + mt * 16 + 8) * stride + c0 + nt * 8) =
                    pack_h2(acc[mt][nt][2], acc[mt][nt][3]);
            }
    }
}

// ================= merged fp16 in-place q+k norm =================
// One block per token row. 256 threads: q row (256 x uint4 = 2048 halves);
// warps 0-1 also handle the k row (64 x uint4 = 512 halves).
__global__ void __launch_bounds__(256) qknorm16()
{
    const size_t row = blockIdx.x;
    const int tid = threadIdx.x;

    uint4* qp = (uint4*)(g_qh + row * C_);
    uint4 vq = qp[tid];
    __half2* hq = (__half2*)&vq;
    float ssq = 0.f;
#pragma unroll
    for (int j = 0; j < 4; j++) {
        float2 f = __half22float2(hq[j]);
        ssq += f.x * f.x + f.y * f.y;
    }

    uint4 vk;
    float ssk = 0.f;
    uint4* kp = (uint4*)(g_kh + row * 512);
    if (tid < 64) {
        vk = kp[tid];
        __half2* hk = (__half2*)&vk;
#pragma unroll
        for (int j = 0; j < 4; j++) {
            float2 f = __half22float2(hk[j]);
            ssk += f.x * f.x + f.y * f.y;
        }
    }

#pragma unroll
    for (int off = 16; off; off >>= 1) ssq += __shfl_xor_sync(0xffffffffu, ssq, off);
    if (tid < 64) {
#pragma unroll
        for (int off = 16; off; off >>= 1) ssk += __shfl_xor_sync(0xffffffffu, ssk, off);
    }

    __shared__ float redq[8], redk[2];
    if ((tid & 31) == 0) {
        redq[tid >> 5] = ssq;
        if (tid < 64) redk[tid >> 5] = ssk;
    }
    __syncthreads();

    float totq = redq[0] + redq[1] + redq[2] + redq[3] +
                 redq[4] + redq[5] + redq[6] + redq[7];
    float scq = 0.08838834764831845f / (sqrtf(totq) + 1e-12f);
#pragma unroll
    for (int j = 0; j < 4; j++) {
        float2 f = __half22float2(hq[j]);
        hq[j] = __float22half2_rn(make_float2(f.x * scq, f.y * scq));
    }
    qp[tid] = vq;

    if (tid < 64) {
        float sck = 1.f / (sqrtf(redk[0] + redk[1]) + 1e-12f);
        __half2* hk = (__half2*)&vk;
#pragma unroll
        for (int j = 0; j < 4; j++) {
            float2 f = __half22float2(hk[j]);
            hk[j] = __float22half2_rn(make_float2(f.x * sck, f.y * sck));
        }
        kp[tid] = vk;
    }
}

// ================= HMMA flash attention (R12/R15 proven, verbatim) =================
__device__ __forceinline__ void load_tile64(uint32_t dstBase, const __half* __restrict__ src,
                                            size_t stride)
{
    int tid = threadIdx.x;
#pragma unroll
    for (int i = 0; i < 8; i++) {
        int lin = tid + 128 * i;
        int r = lin >> 4, ch = lin & 15;
        cp16(dstBase + (ch >> 3) * 8192 + SWZ(r * 128 + (ch & 7) * 16),
             src + (size_t)r * stride + ch * 8);
    }
}

__global__ void __launch_bounds__(128) flash_mma_kernel()
{
    extern __shared__ char sm[];
    uint32_t sb = smem_to_u32(sm);
    const int tid = threadIdx.x, wid = tid >> 5, lane = tid & 31;
    const int qt = blockIdx.x, h = blockIdx.y, b = blockIdx.z, g = h >> 2;
    const int q0 = qt * 64, wm = wid * 16;

    const __half* qsrc = g_qh + ((size_t)(b * T_ + q0)) * C_ + h * HD;
    const __half* ksrc = g_kh + (size_t)b * T_ * 512 + g * HD;
    const __half* vsrc = g_vh + (size_t)b * T_ * 512 + g * HD;

    load_tile64(sb, qsrc, C_);
    CP_COMMIT();
    load_tile64(sb + 16384,         ksrc, 512);
    load_tile64(sb + 16384 + 16384, vsrc, 512);
    CP_COMMIT();
    if (qt >= 1) {
        uint32_t st = sb + 16384 + 32768;
        load_tile64(st,         ksrc + 64 * 512, 512);
        load_tile64(st + 16384, vsrc + 64 * 512, 512);
        CP_COMMIT();
    }
    if (qt >= 1) CP_WAIT2(); else CP_WAIT1();
    __syncthreads();

    uint32_t aqr[8][4];
    const int arow = wm + (lane & 15);
#pragma unroll
    for (int ks = 0; ks < 8; ks++)
        ldm4(aqr[ks], sb + (ks >> 2) * 8192 +
                      SWZ(arow * 128 + (ks & 3) * 32 + ((lane >> 4) & 1) * 16));

    float o[16][4];
#pragma unroll
    for (int i = 0; i < 16; i++)
#pragma unroll
        for (int c = 0; c < 4; c++) o[i][c] = 0.f;
    float l0 = 0.f, l1 = 0.f;

    int stage = 0;
    for (int kt = 0; kt <= qt; kt++) {
        if (kt + 1 <= qt) CP_WAIT1(); else CP_WAIT0();
        __syncthreads();
        if (kt + 2 <= qt) {
            int ps = stage + 2; if (ps >= 3) ps -= 3;
            uint32_t st = sb + 16384 + ps * 32768;
            size_t off = (size_t)(kt + 2) * 64 * 512;
            load_tile64(st,         ksrc + off, 512);
            load_tile64(st + 16384, vsrc + off, 512);
            CP_COMMIT();
        }

        uint32_t Kb = sb + 16384 + stage * 32768;
        uint32_t Vb = Kb + 16384;
        if (++stage == 3) stage = 0;

        float sf[8][4];
#pragma unroll
        for (int f = 0; f < 8; f++)
#pragma unroll
            for (int c = 0; c < 4; c++) sf[f][c] = 0.f;

#pragma unroll
        for (int ks = 0; ks < 8; ks++) {
            const int brow_l = (lane & 7) + 8 * ((lane >> 4) & 1);
            const int bcol   = (ks & 3) * 32 + ((lane >> 3) & 1) * 16;
#pragma unroll
            for (int nf = 0; nf < 4; nf++) {
                uint32_t kb[4];
                ldm4(kb, Kb + (ks >> 2) * 8192 + SWZ((nf * 16 + brow_l) * 128 + bcol));
                mma_f16(sf[2 * nf],     aqr[ks], kb);
                mma_f16(sf[2 * nf + 1], aqr[ks], kb + 2);
            }
        }

        if (kt == qt) {
            const int r0 = wm + (lane >> 2);
            const int cb = (lane & 3) * 2;
#pragma unroll
            for (int f = 0; f < 8; f++)
#pragma unroll
                for (int c = 0; c < 4; c++) {
                    int col = f * 8 + cb + (c & 1);
                    int row = r0 + (c >> 1) * 8;
                    if (col > row) sf[f][c] = -1e30f;
                }
        }

        // fixed-max softmax numerator (scores bounded by l2-norms)
#pragma unroll
        for (int f = 0; f < 8; f++) {
            sf[f][0] = __expf(sf[f][0]);
            sf[f][1] = __expf(sf[f][1]);
            sf[f][2] = __expf(sf[f][2]);
            sf[f][3] = __expf(sf[f][3]);
            l0 += sf[f][0] + sf[f][1];
            l1 += sf[f][2] + sf[f][3];
        }

        uint32_t pa[4][4];
#pragma unroll
        for (int kp = 0; kp < 4; kp++) {
            const int f0 = 2 * kp, f1 = 2 * kp + 1;
#pragma unroll
            for (int half = 0; half < 2; half++) {
                pa[kp][half]     = pack_h2(sf[f0][2 * half], sf[f0][2 * half + 1]);
                pa[kp][2 + half] = pack_h2(sf[f1][2 * half], sf[f1][2 * half + 1]);
            }
        }

        const int krow = (lane & 7) + 8 * ((lane >> 3) & 1);
        const int nadd = 8 * (lane >> 4);
#pragma unroll
        for (int kp = 0; kp < 4; kp++) {
            const int kr = kp * 16 + krow;
#pragma unroll
            for (int nf = 0; nf < 8; nf++) {
                const int n0 = nf * 16;
                const uint32_t voff = ((uint32_t)(n0 >> 6)) * 8192 +
                                      SWZ(kr * 128 + ((n0 & 63) + nadd) * 2);
                uint32_t vb[4];
                ldm4t(vb, Vb + voff);
                mma_f16(o[2 * nf],     pa[kp], vb);
                mma_f16(o[2 * nf + 1], pa[kp], vb + 2);
            }
        }
    }

    l0 += __shfl_xor_sync(0xffffffffu, l0, 1);
    l0 += __shfl_xor_sync(0xffffffffu, l0, 2);
    l1 += __shfl_xor_sync(0xffffffffu, l1, 1);
    l1 += __shfl_xor_sync(0xffffffffu, l1, 2);
    float inv0 = 1.f / l0, inv1 = 1.f / l1;
    size_t row0 = (size_t)(b * T_ + q0 + wm + (lane >> 2));
    int colb = h * HD + (lane & 3) * 2;
#pragma unroll
    for (int nf = 0; nf < 16; nf++) {
        int col = colb + nf * 8;
        *(uint32_t*)(g_yh + row0 * C_ + col) =
            pack_h2(o[nf][0] * inv0, o[nf][1] * inv0);
        *(uint32_t*)(g_yh + (row0 + 8) * C_ + col) =
            pack_h2(o[nf][2] * inv1, o[nf][3] * inv1);
    }
}

// ================= launch =================
extern "C" void kernel_launch(void* const* d_in, const int* in_sizes, int n_in,
                              void* d_out, int out_size)
{
    const float* x     = (const float*)d_in[0];
    const float* Wq    = (const float*)d_in[1];
    const float* Wkv   = (const float*)d_in[2];
    const float* Wproj = (const float*)d_in[3];
    float* out = (float*)d_out;

    __half *xh, *yh, *wqkvt, *wpt;
    cudaGetSymbolAddress((void**)&xh,    g_xh);
    cudaGetSymbolAddress((void**)&yh,    g_yh);
    cudaGetSymbolAddress((void**)&wqkvt, g_wqkvt);
    cudaGetSymbolAddress((void**)&wpt,   g_wpt);

    const int GEMM_SMEM  = 2 * 32768;           // 64 KB -> 3 CTA/SM
    const int FLASH_SMEM = 16384 + 3 * 32768;   // 112 KB -> 2 CTA/SM
    cudaFuncSetAttribute(gemm_mma<0>, cudaFuncAttributeMaxDynamicSharedMemorySize, GEMM_SMEM);
    cudaFuncSetAttribute(gemm_mma<3>, cudaFuncAttributeMaxDynamicSharedMemorySize, GEMM_SMEM);
    cudaFuncSetAttribute(flash_mma_kernel, cudaFuncAttributeMaxDynamicSharedMemorySize, FLASH_SMEM);

    // 1) fused staging: x convert + Wq/Wkv/Wproj transposes (one launch)
    stage_all<<<12288, 256>>>(x, Wq, Wkv, Wproj);

    // 2) fused q/k/v projection (one launch, stacked weights, epilogue select)
    gemm_mma<3><<<dim3(24, 64), 256, GEMM_SMEM>>>(xh, wqkvt, nullptr, C_, 0);

    // 3) merged in-place fp16 l2 norms (q pre-scaled by 1/sqrt(HD))
    qknorm16<<<M_, 256>>>();

    // 4) flash attention -> yh
    flash_mma_kernel<<<dim3(T_ / 64, NH, B_), 128, FLASH_SMEM>>>();

    // 5) out = y @ Wproj (fp32 out)
    gemm_mma<0><<<dim3(16, 64), 256, GEMM_SMEM>>>(yh, wpt, out, C_, C_);
}

// round 17
// speedup vs baseline: 1.0169x; 1.0169x over previous
#include <cuda_runtime.h>
#include <cuda_fp16.h>
#include <math.h>
#include <stdint.h>

#define B_  4
#define T_  2048
#define C_  2048
#define NH  16
#define NKV 4
#define HD  128
#define KVW 1024
#define M_  (B_ * T_)   // 8192

// ---------------- scratch (no allocations allowed) ----------------
__device__ __half g_xh[(size_t)M_ * C_];          // x fp16
__device__ __half g_qh[(size_t)M_ * C_];          // q fp16 (normalized in place)
__device__ __half g_kh[(size_t)M_ * 512];         // k fp16 (normalized in place)
__device__ __half g_vh[(size_t)M_ * 512];         // v fp16
__device__ __half g_yh[(size_t)M_ * C_];          // attn out fp16
__device__ __half g_wqkvt[(size_t)3072 * C_];     // [WqT | WkvT] [N][K]
__device__ __half g_wpt[(size_t)C_ * C_];         // WprojT [N][K]

// ================= helpers =================
__device__ __forceinline__ uint32_t smem_to_u32(const void* p) {
    uint32_t a;
    asm("{ .reg .u64 t; cvta.to.shared.u64 t, %1; cvt.u32.u64 %0, t; }"
        : "=r"(a) : "l"(p));
    return a;
}
#define SWZ(off) ((off) ^ (((off) >> 3) & 0x70))

__device__ __forceinline__ void ldm4(uint32_t* r, uint32_t addr) {
    asm volatile("ldmatrix.sync.aligned.m8n8.x4.shared.b16 {%0,%1,%2,%3}, [%4];"
        : "=r"(r[0]), "=r"(r[1]), "=r"(r[2]), "=r"(r[3]) : "r"(addr));
}
__device__ __forceinline__ void ldm2(uint32_t* r, uint32_t addr) {
    asm volatile("ldmatrix.sync.aligned.m8n8.x2.shared.b16 {%0,%1}, [%2];"
        : "=r"(r[0]), "=r"(r[1]) : "r"(addr));
}
__device__ __forceinline__ void ldm4t(uint32_t* r, uint32_t addr) {
    asm volatile("ldmatrix.sync.aligned.m8n8.x4.trans.shared.b16 {%0,%1,%2,%3}, [%4];"
        : "=r"(r[0]), "=r"(r[1]), "=r"(r[2]), "=r"(r[3]) : "r"(addr));
}
__device__ __forceinline__ void mma_f16(float* c, const uint32_t* a, const uint32_t* b) {
    asm volatile("mma.sync.aligned.m16n8k16.row.col.f32.f16.f16.f32 "
        "{%0,%1,%2,%3}, {%4,%5,%6,%7}, {%8,%9}, {%0,%1,%2,%3};"
        : "+f"(c[0]), "+f"(c[1]), "+f"(c[2]), "+f"(c[3])
        : "r"(a[0]), "r"(a[1]), "r"(a[2]), "r"(a[3]), "r"(b[0]), "r"(b[1]));
}
__device__ __forceinline__ void cp16(uint32_t dst, const void* src) {
    asm volatile("cp.async.cg.shared.global [%0], [%1], 16;" :: "r"(dst), "l"(src));
}
#define CP_COMMIT() asm volatile("cp.async.commit_group;" ::: "memory")
#define CP_WAIT0()  asm volatile("cp.async.wait_group 0;" ::: "memory")
#define CP_WAIT1()  asm volatile("cp.async.wait_group 1;" ::: "memory")

__device__ __forceinline__ uint32_t pack_h2(float x, float y) {
    __half2 t = __float22half2_rn(make_float2(x, y));
    return *(uint32_t*)&t;
}

// ================= fused staging: x convert + 3 weight transposes =================
__device__ __forceinline__ void transpose_tile(const float* __restrict__ W,
                                               __half* __restrict__ Tt,
                                               int K, int N, int n0, int k0, int tid)
{
    __shared__ float t[32][33];
    int tx = tid & 31, ty = tid >> 5;
#pragma unroll
    for (int j = 0; j < 4; j++)
        t[ty + 8 * j][tx] = W[(size_t)(k0 + ty + 8 * j) * N + n0 + tx];
    __syncthreads();
#pragma unroll
    for (int j = 0; j < 4; j++)
        Tt[(size_t)(n0 + ty + 8 * j) * K + k0 + tx] = __float2half_rn(t[tx][ty + 8 * j]);
}

__global__ void __launch_bounds__(256) stage_all(const float* __restrict__ x,
                                                 const float* __restrict__ Wq,
                                                 const float* __restrict__ Wkv,
                                                 const float* __restrict__ Wproj)
{
    const int bid = blockIdx.x, tid = threadIdx.x;
    if (bid < 2048) {
        const float4* src = (const float4*)x;
        uint2* dst = (uint2*)g_xh;
        const int n4 = M_ * C_ / 4;
        for (int i = bid * 256 + tid; i < n4; i += 2048 * 256) {
            float4 v = src[i];
            dst[i] = make_uint2(pack_h2(v.x, v.y), pack_h2(v.z, v.w));
        }
    } else if (bid < 6144) {
        int b = bid - 2048;
        transpose_tile(Wq, g_wqkvt, C_, C_, (b & 63) * 32, (b >> 6) * 32, tid);
    } else if (bid < 8192) {
        int b = bid - 6144;
        transpose_tile(Wkv, g_wqkvt + (size_t)2048 * C_, C_, KVW,
                       (b & 31) * 32, (b >> 5) * 32, tid);
    } else {
        int b = bid - 8192;
        transpose_tile(Wproj, g_wpt, C_, C_, (b & 63) * 32, (b >> 6) * 32, tid);
    }
}

// ================= HMMA fp16 GEMM, 2-stage (R12 mainloop) =================
__device__ __forceinline__ void cp_panel(uint32_t dstBase, const __half* __restrict__ src,
                                         int ldk, int row0, int k0)
{
    int tid = threadIdx.x;
#pragma unroll
    for (int i = 0; i < 4; i++) {
        int l = tid + 256 * i;
        int r = l >> 3, ch = l & 7;
        cp16(dstBase + SWZ(r * 128 + ch * 16), src + (size_t)(row0 + r) * ldk + k0 + ch * 8);
    }
}

template<int MODE>
__global__ void __launch_bounds__(256) gemm_mma(const __half* __restrict__ A,
                                                const __half* __restrict__ Bt,
                                                void* __restrict__ outp,
                                                int K, int No)
{
    extern __shared__ char sm[];
    uint32_t sb = smem_to_u32(sm);
    const int tid = threadIdx.x, wid = tid >> 5, lane = tid & 31;
    const int row0 = blockIdx.y * 128, col0 = blockIdx.x * 128;
    const int wm = (wid >> 2) * 64;
    const int wn = (wid & 3) * 32;

    float acc[4][4][4];
#pragma unroll
    for (int a = 0; a < 4; a++)
#pragma unroll
        for (int b = 0; b < 4; b++)
#pragma unroll
            for (int c = 0; c < 4; c++) acc[a][b][c] = 0.f;

    const int KIT = K >> 6;
#pragma unroll
    for (int p = 0; p < 2; p++) {
        uint32_t st = sb + p * 32768;
        cp_panel(st,         A,  K, row0, p * 64);
        cp_panel(st + 16384, Bt, K, col0, p * 64);
        CP_COMMIT();
    }

    for (int kc = 0; kc < KIT; kc++) {
        if (kc == KIT - 1) CP_WAIT0(); else CP_WAIT1();
        __syncthreads();

        uint32_t st = sb + (kc & 1) * 32768;
#pragma unroll
        for (int ks = 0; ks < 4; ks++) {
            uint32_t af[4][4], bf[4][2];
            const int arow = wm + (lane & 15);
            const int acol = ks * 32 + ((lane >> 4) & 1) * 16;
#pragma unroll
            for (int mt = 0; mt < 4; mt++)
                ldm4(af[mt], st + SWZ((uint32_t)(arow + mt * 16) * 128 + acol));
            const int brow = wn + (lane & 7);
            const int bcol = ks * 32 + ((lane >> 3) & 1) * 16;
#pragma unroll
            for (int nt = 0; nt < 4; nt++)
                ldm2(bf[nt], st + 16384 + SWZ((uint32_t)(brow + nt * 8) * 128 + bcol));
#pragma unroll
            for (int mt = 0; mt < 4; mt++)
#pragma unroll
                for (int nt = 0; nt < 4; nt++)
                    mma_f16(acc[mt][nt], af[mt], bf[nt]);
        }
        __syncthreads();

        if (kc + 2 < KIT) {
            uint32_t st2 = sb + (kc & 1) * 32768;
            int k0 = (kc + 2) * 64;
            cp_panel(st2,         A,  K, row0, k0);
            cp_panel(st2 + 16384, Bt, K, col0, k0);
            CP_COMMIT();
        }
    }

    const int r0 = row0 + wm + (lane >> 2);
    if (MODE == 0) {
        float* o = (float*)outp;
        const int c0 = col0 + wn + (lane & 3) * 2;
#pragma unroll
        for (int mt = 0; mt < 4; mt++)
#pragma unroll
            for (int nt = 0; nt < 4; nt++) {
                *(float2*)(o + (size_t)(r0 + mt * 16) * No + c0 + nt * 8) =
                    make_float2(acc[mt][nt][0], acc[mt][nt][1]);
                *(float2*)(o + (size_t)(r0 + mt * 16 + 8) * No + c0 + nt * 8) =
                    make_float2(acc[mt][nt][2], acc[mt][nt][3]);
            }
    } else {
        __half* o;
        int stride, cbase;
        if (col0 < 2048)      { o = g_qh; stride = C_;  cbase = col0; }
        else if (col0 < 2560) { o = g_kh; stride = 512; cbase = col0 - 2048; }
        else                  { o = g_vh; stride = 512; cbase = col0 - 2560; }
        const int c0 = cbase + wn + (lane & 3) * 2;
#pragma unroll
        for (int mt = 0; mt < 4; mt++)
#pragma unroll
            for (int nt = 0; nt < 4; nt++) {
                *(uint32_t*)(o + (size_t)(r0 + mt * 16) * stride + c0 + nt * 8) =
                    pack_h2(acc[mt][nt][0], acc[mt][nt][1]);
                *(uint32_t*)(o + (size_t)(r0 + mt * 16 + 8) * stride + c0 + nt * 8) =
                    pack_h2(acc[mt][nt][2], acc[mt][nt][3]);
            }
    }
}

// ================= merged fp16 in-place q+k norm =================
__global__ void __launch_bounds__(256) qknorm16()
{
    const size_t row = blockIdx.x;
    const int tid = threadIdx.x;

    uint4* qp = (uint4*)(g_qh + row * C_);
    uint4 vq = qp[tid];
    __half2* hq = (__half2*)&vq;
    float ssq = 0.f;
#pragma unroll
    for (int j = 0; j < 4; j++) {
        float2 f = __half22float2(hq[j]);
        ssq += f.x * f.x + f.y * f.y;
    }

    uint4 vk;
    float ssk = 0.f;
    uint4* kp = (uint4*)(g_kh + row * 512);
    if (tid < 64) {
        vk = kp[tid];
        __half2* hk = (__half2*)&vk;
#pragma unroll
        for (int j = 0; j < 4; j++) {
            float2 f = __half22float2(hk[j]);
            ssk += f.x * f.x + f.y * f.y;
        }
    }

#pragma unroll
    for (int off = 16; off; off >>= 1) ssq += __shfl_xor_sync(0xffffffffu, ssq, off);
    if (tid < 64) {
#pragma unroll
        for (int off = 16; off; off >>= 1) ssk += __shfl_xor_sync(0xffffffffu, ssk, off);
    }

    __shared__ float redq[8], redk[2];
    if ((tid & 31) == 0) {
        redq[tid >> 5] = ssq;
        if (tid < 64) redk[tid >> 5] = ssk;
    }
    __syncthreads();

    float totq = redq[0] + redq[1] + redq[2] + redq[3] +
                 redq[4] + redq[5] + redq[6] + redq[7];
    float scq = 0.08838834764831845f / (sqrtf(totq) + 1e-12f);
#pragma unroll
    for (int j = 0; j < 4; j++) {
        float2 f = __half22float2(hq[j]);
        hq[j] = __float22half2_rn(make_float2(f.x * scq, f.y * scq));
    }
    qp[tid] = vq;

    if (tid < 64) {
        float sck = 1.f / (sqrtf(redk[0] + redk[1]) + 1e-12f);
        __half2* hk = (__half2*)&vk;
#pragma unroll
        for (int j = 0; j < 4; j++) {
            float2 f = __half22float2(hk[j]);
            hk[j] = __float22half2_rn(make_float2(f.x * sck, f.y * sck));
        }
        kp[tid] = vk;
    }
}

// ================= HMMA flash attention: 2-stage ring reusing Q buffer =================
// smem = 2 x 32KB = 64KB -> 3 CTAs/SM (12 warps). Q loaded into ring0, hoisted to
// registers, then ring0 joins the KV double-buffer. Tile kt lives in ring[(kt+1)&1].
__device__ __forceinline__ void load_tile64(uint32_t dstBase, const __half* __restrict__ src,
                                            size_t stride)
{
    int tid = threadIdx.x;
#pragma unroll
    for (int i = 0; i < 8; i++) {
        int lin = tid + 128 * i;
        int r = lin >> 4, ch = lin & 15;
        cp16(dstBase + (ch >> 3) * 8192 + SWZ(r * 128 + (ch & 7) * 16),
             src + (size_t)r * stride + ch * 8);
    }
}

__global__ void __launch_bounds__(128, 3) flash_mma_kernel()
{
    extern __shared__ char sm[];
    uint32_t sb = smem_to_u32(sm);
    const int tid = threadIdx.x, wid = tid >> 5, lane = tid & 31;
    const int qt = blockIdx.x, h = blockIdx.y, b = blockIdx.z, g = h >> 2;
    const int q0 = qt * 64, wm = wid * 16;

    const __half* qsrc = g_qh + ((size_t)(b * T_ + q0)) * C_ + h * HD;
    const __half* ksrc = g_kh + (size_t)b * T_ * 512 + g * HD;
    const __half* vsrc = g_vh + (size_t)b * T_ * 512 + g * HD;

    // prologue: KV0 -> ring1 (group), Q -> ring0 (group); wait both, hoist Q.
    load_tile64(sb + 32768,         ksrc, 512);
    load_tile64(sb + 32768 + 16384, vsrc, 512);
    CP_COMMIT();
    load_tile64(sb, qsrc, C_);
    CP_COMMIT();
    CP_WAIT0();
    __syncthreads();

    uint32_t aqr[8][4];
    const int arow = wm + (lane & 15);
#pragma unroll
    for (int ks = 0; ks < 8; ks++)
        ldm4(aqr[ks], sb + (ks >> 2) * 8192 +
                      SWZ(arow * 128 + (ks & 3) * 32 + ((lane >> 4) & 1) * 16));
    __syncthreads();                       // Q consumed; ring0 free for KV1

    if (qt >= 1) {
        load_tile64(sb,         ksrc + 64 * 512, 512);
        load_tile64(sb + 16384, vsrc + 64 * 512, 512);
        CP_COMMIT();
    }

    float o[16][4];
#pragma unroll
    for (int i = 0; i < 16; i++)
#pragma unroll
        for (int c = 0; c < 4; c++) o[i][c] = 0.f;
    float l0 = 0.f, l1 = 0.f;

    for (int kt = 0; kt <= qt; kt++) {
        if (kt < qt) CP_WAIT1(); else CP_WAIT0();   // tile kt ready
        __syncthreads();

        uint32_t Kb = sb + (((kt + 1) & 1)) * 32768;
        uint32_t Vb = Kb + 16384;

        // ---- S = Q K^T ----
        float sf[8][4];
#pragma unroll
        for (int f = 0; f < 8; f++)
#pragma unroll
            for (int c = 0; c < 4; c++) sf[f][c] = 0.f;

#pragma unroll
        for (int ks = 0; ks < 8; ks++) {
            const int brow_l = (lane & 7) + 8 * ((lane >> 4) & 1);
            const int bcol   = (ks & 3) * 32 + ((lane >> 3) & 1) * 16;
#pragma unroll
            for (int nf = 0; nf < 4; nf++) {
                uint32_t kb[4];
                ldm4(kb, Kb + (ks >> 2) * 8192 + SWZ((nf * 16 + brow_l) * 128 + bcol));
                mma_f16(sf[2 * nf],     aqr[ks], kb);
                mma_f16(sf[2 * nf + 1], aqr[ks], kb + 2);
            }
        }

        if (kt == qt) {
            const int r0 = wm + (lane >> 2);
            const int cb = (lane & 3) * 2;
#pragma unroll
            for (int f = 0; f < 8; f++)
#pragma unroll
                for (int c = 0; c < 4; c++) {
                    int col = f * 8 + cb + (c & 1);
                    int row = r0 + (c >> 1) * 8;
                    if (col > row) sf[f][c] = -1e30f;
                }
        }

        // fixed-max softmax numerator (scores bounded by l2-norms)
#pragma unroll
        for (int f = 0; f < 8; f++) {
            sf[f][0] = __expf(sf[f][0]);
            sf[f][1] = __expf(sf[f][1]);
            sf[f][2] = __expf(sf[f][2]);
            sf[f][3] = __expf(sf[f][3]);
            l0 += sf[f][0] + sf[f][1];
            l1 += sf[f][2] + sf[f][3];
        }

        uint32_t pa[4][4];
#pragma unroll
        for (int kp = 0; kp < 4; kp++) {
            const int f0 = 2 * kp, f1 = 2 * kp + 1;
#pragma unroll
            for (int half = 0; half < 2; half++) {
                pa[kp][half]     = pack_h2(sf[f0][2 * half], sf[f0][2 * half + 1]);
                pa[kp][2 + half] = pack_h2(sf[f1][2 * half], sf[f1][2 * half + 1]);
            }
        }

        // ---- O += P V ----
        const int krow = (lane & 7) + 8 * ((lane >> 3) & 1);
        const int nadd = 8 * (lane >> 4);
#pragma unroll
        for (int kp = 0; kp < 4; kp++) {
            const int kr = kp * 16 + krow;
#pragma unroll
            for (int nf = 0; nf < 8; nf++) {
                const int n0 = nf * 16;
                const uint32_t voff = ((uint32_t)(n0 >> 6)) * 8192 +
                                      SWZ(kr * 128 + ((n0 & 63) + nadd) * 2);
                uint32_t vb[4];
                ldm4t(vb, Vb + voff);
                mma_f16(o[2 * nf],     pa[kp], vb);
                mma_f16(o[2 * nf + 1], pa[kp], vb + 2);
            }
        }

        __syncthreads();                    // all warps done reading tile kt
        if (kt + 2 <= qt) {                 // prefetch kt+2 into the freed buffer
            size_t off = (size_t)(kt + 2) * 64 * 512;
            uint32_t st = sb + ((kt + 1) & 1) * 32768;
            load_tile64(st,         ksrc + off, 512);
            load_tile64(st + 16384, vsrc + off, 512);
            CP_COMMIT();
        }
    }

    l0 += __shfl_xor_sync(0xffffffffu, l0, 1);
    l0 += __shfl_xor_sync(0xffffffffu, l0, 2);
    l1 += __shfl_xor_sync(0xffffffffu, l1, 1);
    l1 += __shfl_xor_sync(0xffffffffu, l1, 2);
    float inv0 = 1.f / l0, inv1 = 1.f / l1;
    size_t row0 = (size_t)(b * T_ + q0 + wm + (lane >> 2));
    int colb = h * HD + (lane & 3) * 2;
#pragma unroll
    for (int nf = 0; nf < 16; nf++) {
        int col = colb + nf * 8;
        *(uint32_t*)(g_yh + row0 * C_ + col) =
            pack_h2(o[nf][0] * inv0, o[nf][1] * inv0);
        *(uint32_t*)(g_yh + (row0 + 8) * C_ + col) =
            pack_h2(o[nf][2] * inv1, o[nf][3] * inv1);
    }
}

// ================= launch =================
extern "C" void kernel_launch(void* const* d_in, const int* in_sizes, int n_in,
                              void* d_out, int out_size)
{
    const float* x     = (const float*)d_in[0];
    const float* Wq    = (const float*)d_in[1];
    const float* Wkv   = (const float*)d_in[2];
    const float* Wproj = (const float*)d_in[3];
    float* out = (float*)d_out;

    __half *xh, *yh, *wqkvt, *wpt;
    cudaGetSymbolAddress((void**)&xh,    g_xh);
    cudaGetSymbolAddress((void**)&yh,    g_yh);
    cudaGetSymbolAddress((void**)&wqkvt, g_wqkvt);
    cudaGetSymbolAddress((void**)&wpt,   g_wpt);

    const int GEMM_SMEM  = 2 * 32768;   // 64 KB -> 3 CTA/SM
    const int FLASH_SMEM = 2 * 32768;   // 64 KB -> 3 CTA/SM (Q buffer reused in ring)
    cudaFuncSetAttribute(gemm_mma<0>, cudaFuncAttributeMaxDynamicSharedMemorySize, GEMM_SMEM);
    cudaFuncSetAttribute(gemm_mma<3>, cudaFuncAttributeMaxDynamicSharedMemorySize, GEMM_SMEM);
    cudaFuncSetAttribute(flash_mma_kernel, cudaFuncAttributeMaxDynamicSharedMemorySize, FLASH_SMEM);

    // 1) fused staging: x convert + Wq/Wkv/Wproj transposes (one launch)
    stage_all<<<12288, 256>>>(x, Wq, Wkv, Wproj);

    // 2) fused q/k/v projection (one launch, stacked weights, epilogue select)
    gemm_mma<3><<<dim3(24, 64), 256, GEMM_SMEM>>>(xh, wqkvt, nullptr, C_, 0);

    // 3) merged in-place fp16 l2 norms (q pre-scaled by 1/sqrt(HD))
    qknorm16<<<M_, 256>>>();

    // 4) flash attention -> yh (64 KB smem, 3 CTAs/SM)
    flash_mma_kernel<<<dim3(T_ / 64, NH, B_), 128, FLASH_SMEM>>>();

    // 5) out = y @ Wproj (fp32 out)
    gemm_mma<0><<<dim3(16, 64), 256, GEMM_SMEM>>>(yh, wpt, out, C_, C_);
}